// round 5
// baseline (speedup 1.0000x reference)
#include <cuda_runtime.h>
#include <cuda_bf16.h>

#define T_DIM 8192
#define K_DIM 2048
#define TM1   (T_DIM - 1)                      // 8191 rows in the loss
#define NTOT  ((long long)TM1 * K_DIM)         // 16,775,168 elements
#define GAMMA 0.99f
#define LOGG  (-0.0100503358535014f)           // logf(0.99)

#define NCHUNK       ((TM1 + 31) / 32)         // 256 row-chunks per column
#define SCAN_BLOCKS  256                       // 256 blocks * 8 warps = 2048 columns
#define QSUM_BLOCKS  928
#define NBLOCKS      (SCAN_BLOCKS + QSUM_BLOCKS)   // 1184 = 8 blocks/SM * 148 SMs
// Interleave: in every group of 74 block IDs, the first 16 are scan blocks.
// 1184/74 = 16 groups -> 256 scan, 928 qsum, spread evenly across SMs.
#define GROUP        74
#define SCAN_PER_G   16
#define FULLM        0xFFFFFFFFu

// Scratch (device globals are the allowed scratch mechanism).
// Transposed layout [k][t] so warp-over-rows access is coalesced.
__device__ float2       g_dp  [(long long)K_DIM * TM1];  // {decay, td*decay}
__device__ double       g_part[NBLOCKS];
__device__ unsigned int g_done;                          // zero-init; self-resetting

// smooth-L1: |d|<1 ? 0.5 d^2 : |d|-0.5  ==  m*(a - 0.5m) with a=|d|, m=min(a,1)
//   (a<1: m=a -> a*(a-0.5a)=0.5a^2 ; a>=1: m=1 -> a-0.5). Branch-free, 3 SASS ops.
__device__ __forceinline__ float sl1(float pred, float target) {
    float a = fabsf(pred - target);
    float m = fminf(a, 1.0f);
    return m * (a - 0.5f * m);
}
// fused accumulate version: acc += sl1(d)
__device__ __forceinline__ float sl1_acc(float acc, float d) {
    float a = fabsf(d);
    float m = fminf(a, 1.0f);
    return fmaf(m, fmaf(-0.5f, m, a), acc);
}

__global__ void __launch_bounds__(256, 8)
retrace_main(const float* __restrict__ q,
             const float* __restrict__ tq,
             const float* __restrict__ tv,
             const float* __restrict__ r,
             const float* __restrict__ olp,
             const float* __restrict__ tlp,
             float* __restrict__ out)
{
    const int tid  = threadIdx.x;
    const int lane = tid & 31;
    const int wrp  = tid >> 5;
    const int grp  = blockIdx.x / GROUP;
    const int gin  = blockIdx.x % GROUP;
    const bool is_scan = gin < SCAN_PER_G;
    double acc = 0.0;

    if (is_scan) {
        // ============ one WARP per column; lanes cover 32 consecutive rows ============
        // 8 warps per block cover columns k..k+7 -> together they consume full 32B
        // sectors of the strided row loads (sector = 8 adjacent-k floats).
        const int scan_id = grp * SCAN_PER_G + gin;      // 0..255
        const int k = scan_id * 8 + wrp;

        float carry = 0.0f;          // running log(decay) at end of previous chunk
        int   tstop = TM1;           // first row with decay == 0 (exclusive bound)

        // ---- forward: log-space prefix-sum per chunk, double-buffered loads ----
        auto loadch = [&](int cc, float& liw, float& rr, float& tvv, float& tqq) {
            const int  t = cc * 32 + lane;
            const bool v = t < TM1;
            const size_t o1 = (size_t)(t + 1) * K_DIM + k;
            const size_t o0 = (size_t)t       * K_DIM + k;
            liw = v ? (tlp[o1] - olp[t + 1]) : 0.0f;
            rr  = v ? r [o0] : 0.0f;
            tvv = v ? tv[o1] : 0.0f;
            tqq = v ? tq[o1] : 0.0f;
        };
        auto compch = [&](int cc, float liw, float rr, float tvv, float tqq) -> bool {
            const int  t = cc * 32 + lane;
            const bool v = t < TM1;
            float m    = fminf(liw, 0.0f);
            float iw   = expf(m);
            float s    = v ? (LOGG + m) : 0.0f;
            #pragma unroll
            for (int off = 1; off < 32; off <<= 1) {    // inclusive prefix sum
                float u = __shfl_up_sync(FULLM, s, off);
                if (lane >= off) s += u;
            }
            float ls    = carry + s;
            float decay = expf(ls);                      // underflows to exact 0
            float pdv   = (rr + GAMMA * (tvv - iw * tqq)) * decay;
            if (v) g_dp[(size_t)k * TM1 + t] = make_float2(decay, pdv);
            carry = __shfl_sync(FULLM, ls, 31);
            unsigned bal = __ballot_sync(FULLM, v && decay == 0.0f);
            if (bal) { tstop = cc * 32 + (__ffs(bal) - 1); return true; }
            return false;
        };

        {
            float lA, rA, vA, qA, lB, rB, vB, qB;
            loadch(0, lA, rA, vA, qA);
            int  cc = 0;
            while (true) {
                if (cc + 1 < NCHUNK) loadch(cc + 1, lB, rB, vB, qB);
                if (compch(cc, lA, rA, vA, qA)) break;
                if (++cc >= NCHUNK) break;
                if (cc + 1 < NCHUNK) loadch(cc + 1, lA, rA, vA, qA);
                if (compch(cc, lB, rB, vB, qB)) break;
                if (++cc >= NCHUNK) break;
            }
        }

        // ---- backward: warp suffix-sum of pd per chunk, from last active chunk ----
        // Rows in [tstop, chunk_end) were written with decay=0, pd=0 -> retr==0 ->
        // correction exactly 0, so no extra predicate needed beyond t < TM1.
        const int nch = (tstop + 31) >> 5;
        float Rcarry = 0.0f;
        for (int cc = nch - 1; cc >= 0; --cc) {
            const int  t = cc * 32 + lane;
            const bool v = t < TM1;
            float2 dp = v ? g_dp[(size_t)k * TM1 + t] : make_float2(0.0f, 0.0f);
            float  qv = v ? q[(size_t)t * K_DIM + k]  : 0.0f;
            float  s  = dp.y;
            #pragma unroll
            for (int off = 1; off < 32; off <<= 1) {    // inclusive suffix sum
                float u = __shfl_down_sync(FULLM, s, off);
                if (lane + off < 32) s += u;
            }
            float R    = s + Rcarry;                     // sum over all rows >= t
            float retr = R / fmaxf(dp.x, 1e-10f);
            if (v) acc += (double)(sl1(qv, retr) - sl1(qv, 0.0f));
            Rcarry = __shfl_sync(FULLM, R, 0);
        }
    } else {
        // ------- elementwise sum of sl1(q, 0) over q[0 : TM1*K), MLP=4 -------
        const int qsum_id = grp * (GROUP - SCAN_PER_G) + (gin - SCAN_PER_G); // 0..927
        const long long nvec   = NTOT / 4;               // divisible: K%4==0
        const float4*   q4     = (const float4*)q;
        long long       idx    = (long long)qsum_id * 256 + tid;
        const long long stride = (long long)QSUM_BLOCKS * 256;
        float f0 = 0.0f, f1 = 0.0f, f2 = 0.0f, f3 = 0.0f;
        for (; idx + 3 * stride < nvec; idx += 4 * stride) {
            float4 a = q4[idx];
            float4 b = q4[idx + stride];
            float4 c = q4[idx + 2 * stride];
            float4 d = q4[idx + 3 * stride];
            f0 = sl1_acc(sl1_acc(sl1_acc(sl1_acc(f0, a.x), a.y), a.z), a.w);
            f1 = sl1_acc(sl1_acc(sl1_acc(sl1_acc(f1, b.x), b.y), b.z), b.w);
            f2 = sl1_acc(sl1_acc(sl1_acc(sl1_acc(f2, c.x), c.y), c.z), c.w);
            f3 = sl1_acc(sl1_acc(sl1_acc(sl1_acc(f3, d.x), d.y), d.z), d.w);
        }
        for (; idx < nvec; idx += stride) {
            float4 a = q4[idx];
            f0 = sl1_acc(sl1_acc(sl1_acc(sl1_acc(f0, a.x), a.y), a.z), a.w);
        }
        acc = (double)((f0 + f1) + (f2 + f3));
    }

    // ---- deterministic block reduction: warp shuffle tree + fixed-order sum ----
    __shared__ double shw[8];
    #pragma unroll
    for (int off = 16; off > 0; off >>= 1)
        acc += __shfl_xor_sync(FULLM, acc, off);
    if (lane == 0) shw[wrp] = acc;
    __syncthreads();
    double blocksum = 0.0;
    if (tid == 0) {
        #pragma unroll
        for (int i = 0; i < 8; ++i) blocksum += shw[i];
    }

    // ---- fused last-block finalize (deterministic fixed-order final sum) ----
    __shared__ unsigned int sticket;
    if (tid == 0) {
        g_part[blockIdx.x] = blocksum;
        __threadfence();
        sticket = atomicAdd(&g_done, 1u);
    }
    __syncthreads();
    if (sticket == NBLOCKS - 1) {
        __threadfence();
        double a = 0.0;
        for (int i = tid; i < NBLOCKS; i += 256) a += g_part[i];
        __shared__ double sh[256];
        sh[tid] = a;
        __syncthreads();
        #pragma unroll
        for (int s = 128; s > 0; s >>= 1) {
            if (tid < s) sh[tid] += sh[tid + s];
            __syncthreads();
        }
        if (tid == 0) {
            out[0] = (float)(sh[0] / (double)NTOT);
            g_done = 0;                        // reset for next graph replay
        }
    }
}

extern "C" void kernel_launch(void* const* d_in, const int* in_sizes, int n_in,
                              void* d_out, int out_size)
{
    const float* q   = (const float*)d_in[0];  // state_trajectory_action_values (T,K)
    const float* tq  = (const float*)d_in[1];  // target_state_trajectory_action_values (T,K)
    const float* tv  = (const float*)d_in[2];  // target_expected_state_values (T,K)
    const float* r   = (const float*)d_in[3];  // rewards (T,K)
    const float* olp = (const float*)d_in[4];  // original_log_trajectory_action_probs (T,)
    const float* tlp = (const float*)d_in[5];  // target_log_trajectory_task_action_probs (T,K)
    float* out = (float*)d_out;

    retrace_main<<<NBLOCKS, 256>>>(q, tq, tv, r, olp, tlp, out);
}

// round 6
// speedup vs baseline: 1.8653x; 1.8653x over previous
#include <cuda_runtime.h>
#include <cuda_bf16.h>

#define T_DIM 8192
#define K_DIM 2048
#define TM1   (T_DIM - 1)                      // 8191 rows in the loss
#define NTOT  ((long long)TM1 * K_DIM)         // 16,775,168 elements
#define GAMMA 0.99f
#define LOGG  (-0.0100503358535014f)           // logf(0.99)

#define NCHUNK       ((TM1 + 31) / 32)         // 256 row-chunks per column
#define SCAN_BLOCKS  256                       // FIRST 256 block IDs -> bid%148 covers all SMs
#define QSUM_BLOCKS  888
#define NBLOCKS      (SCAN_BLOCKS + QSUM_BLOCKS)   // 1144 <= 1184 = one full wave @ 8/SM
#define FULLM        0xFFFFFFFFu

// Scratch (device globals are the allowed scratch mechanism).
// Transposed layout [k][t] so warp-over-rows access is coalesced.
__device__ float2       g_dp  [(long long)K_DIM * TM1];  // {decay, td*decay}
__device__ double       g_part[NBLOCKS];
__device__ unsigned int g_done;                          // zero-init; self-resetting

// smooth-L1: |d|<1 ? 0.5 d^2 : |d|-0.5  ==  m*(a - 0.5m) with a=|d|, m=min(a,1)
__device__ __forceinline__ float sl1(float pred, float target) {
    float a = fabsf(pred - target);
    float m = fminf(a, 1.0f);
    return m * (a - 0.5f * m);
}
// fused accumulate version: acc += sl1(d)   (FMNMX + 2x FFMA)
__device__ __forceinline__ float sl1_acc(float acc, float d) {
    float a = fabsf(d);
    float m = fminf(a, 1.0f);
    return fmaf(m, fmaf(-0.5f, m, a), acc);
}

__global__ void __launch_bounds__(256, 8)
retrace_main(const float* __restrict__ q,
             const float* __restrict__ tq,
             const float* __restrict__ tv,
             const float* __restrict__ r,
             const float* __restrict__ olp,
             const float* __restrict__ tlp,
             float* __restrict__ out)
{
    const int tid  = threadIdx.x;
    const int lane = tid & 31;
    const int wrp  = tid >> 5;
    double acc = 0.0;

    if (blockIdx.x < SCAN_BLOCKS) {
        // ============ one WARP per column; lanes cover 32 consecutive rows ============
        // 8 warps per block cover columns k..k+7 -> together they consume full 32B
        // sectors of the strided row loads (sector = 8 adjacent-k floats).
        const int k = blockIdx.x * 8 + wrp;

        float carry = 0.0f;          // running log(decay) at end of previous chunk
        int   tstop = TM1;           // first row with decay == 0 (exclusive bound)

        // ---- forward: log-space prefix-sum per chunk, double-buffered loads ----
        auto loadch = [&](int cc, float& liw, float& rr, float& tvv, float& tqq) {
            const int  t = cc * 32 + lane;
            const bool v = t < TM1;
            const size_t o1 = (size_t)(t + 1) * K_DIM + k;
            const size_t o0 = (size_t)t       * K_DIM + k;
            liw = v ? (tlp[o1] - olp[t + 1]) : 0.0f;
            rr  = v ? r [o0] : 0.0f;
            tvv = v ? tv[o1] : 0.0f;
            tqq = v ? tq[o1] : 0.0f;
        };
        auto compch = [&](int cc, float liw, float rr, float tvv, float tqq) -> bool {
            const int  t = cc * 32 + lane;
            const bool v = t < TM1;
            float m    = fminf(liw, 0.0f);
            float iw   = expf(m);
            float s    = v ? (LOGG + m) : 0.0f;
            #pragma unroll
            for (int off = 1; off < 32; off <<= 1) {    // inclusive prefix sum
                float u = __shfl_up_sync(FULLM, s, off);
                if (lane >= off) s += u;
            }
            float ls    = carry + s;
            float decay = expf(ls);                      // underflows to exact 0
            float pdv   = (rr + GAMMA * (tvv - iw * tqq)) * decay;
            if (v) g_dp[(size_t)k * TM1 + t] = make_float2(decay, pdv);
            carry = __shfl_sync(FULLM, ls, 31);
            unsigned bal = __ballot_sync(FULLM, v && decay == 0.0f);
            if (bal) { tstop = cc * 32 + (__ffs(bal) - 1); return true; }
            return false;
        };

        {
            float lA, rA, vA, qA, lB, rB, vB, qB;
            loadch(0, lA, rA, vA, qA);
            int  cc = 0;
            while (true) {
                if (cc + 1 < NCHUNK) loadch(cc + 1, lB, rB, vB, qB);
                if (compch(cc, lA, rA, vA, qA)) break;
                if (++cc >= NCHUNK) break;
                if (cc + 1 < NCHUNK) loadch(cc + 1, lA, rA, vA, qA);
                if (compch(cc, lB, rB, vB, qB)) break;
                if (++cc >= NCHUNK) break;
            }
        }

        // ---- backward: warp suffix-sum of pd per chunk, from last active chunk ----
        // Rows in [tstop, chunk_end) were written with decay=0, pd=0 -> retr==0 ->
        // correction exactly 0, so no extra predicate needed beyond t < TM1.
        const int nch = (tstop + 31) >> 5;
        float Rcarry = 0.0f;
        for (int cc = nch - 1; cc >= 0; --cc) {
            const int  t = cc * 32 + lane;
            const bool v = t < TM1;
            float2 dp = v ? g_dp[(size_t)k * TM1 + t] : make_float2(0.0f, 0.0f);
            float  qv = v ? q[(size_t)t * K_DIM + k]  : 0.0f;
            float  s  = dp.y;
            #pragma unroll
            for (int off = 1; off < 32; off <<= 1) {    // inclusive suffix sum
                float u = __shfl_down_sync(FULLM, s, off);
                if (lane + off < 32) s += u;
            }
            float R    = s + Rcarry;                     // sum over all rows >= t
            float retr = R / fmaxf(dp.x, 1e-10f);
            if (v) acc += (double)(sl1(qv, retr) - sl1(qv, 0.0f));
            Rcarry = __shfl_sync(FULLM, R, 0);
        }
    } else {
        // ------- elementwise sum of sl1(q, 0) over q[0 : TM1*K), MLP=4 -------
        const long long nvec   = NTOT / 4;               // divisible: K%4==0
        const float4*   q4     = (const float4*)q;
        long long       idx    = (long long)(blockIdx.x - SCAN_BLOCKS) * 256 + tid;
        const long long stride = (long long)QSUM_BLOCKS * 256;
        float f0 = 0.0f, f1 = 0.0f, f2 = 0.0f, f3 = 0.0f;
        for (; idx + 3 * stride < nvec; idx += 4 * stride) {
            float4 a = q4[idx];
            float4 b = q4[idx + stride];
            float4 c = q4[idx + 2 * stride];
            float4 d = q4[idx + 3 * stride];
            f0 = sl1_acc(sl1_acc(sl1_acc(sl1_acc(f0, a.x), a.y), a.z), a.w);
            f1 = sl1_acc(sl1_acc(sl1_acc(sl1_acc(f1, b.x), b.y), b.z), b.w);
            f2 = sl1_acc(sl1_acc(sl1_acc(sl1_acc(f2, c.x), c.y), c.z), c.w);
            f3 = sl1_acc(sl1_acc(sl1_acc(sl1_acc(f3, d.x), d.y), d.z), d.w);
        }
        for (; idx < nvec; idx += stride) {
            float4 a = q4[idx];
            f0 = sl1_acc(sl1_acc(sl1_acc(sl1_acc(f0, a.x), a.y), a.z), a.w);
        }
        acc = (double)((f0 + f1) + (f2 + f3));
    }

    // ---- deterministic block reduction: warp shuffle tree + fixed-order sum ----
    __shared__ double shw[8];
    #pragma unroll
    for (int off = 16; off > 0; off >>= 1)
        acc += __shfl_xor_sync(FULLM, acc, off);
    if (lane == 0) shw[wrp] = acc;
    __syncthreads();
    double blocksum = 0.0;
    if (tid == 0) {
        #pragma unroll
        for (int i = 0; i < 8; ++i) blocksum += shw[i];
    }

    // ---- fused last-block finalize (deterministic fixed-order final sum) ----
    __shared__ unsigned int sticket;
    if (tid == 0) {
        g_part[blockIdx.x] = blocksum;
        __threadfence();
        sticket = atomicAdd(&g_done, 1u);
    }
    __syncthreads();
    if (sticket == NBLOCKS - 1) {
        __threadfence();
        double a = 0.0;
        for (int i = tid; i < NBLOCKS; i += 256) a += g_part[i];
        __shared__ double sh[256];
        sh[tid] = a;
        __syncthreads();
        #pragma unroll
        for (int s = 128; s > 0; s >>= 1) {
            if (tid < s) sh[tid] += sh[tid + s];
            __syncthreads();
        }
        if (tid == 0) {
            out[0] = (float)(sh[0] / (double)NTOT);
            g_done = 0;                        // reset for next graph replay
        }
    }
}

extern "C" void kernel_launch(void* const* d_in, const int* in_sizes, int n_in,
                              void* d_out, int out_size)
{
    const float* q   = (const float*)d_in[0];  // state_trajectory_action_values (T,K)
    const float* tq  = (const float*)d_in[1];  // target_state_trajectory_action_values (T,K)
    const float* tv  = (const float*)d_in[2];  // target_expected_state_values (T,K)
    const float* r   = (const float*)d_in[3];  // rewards (T,K)
    const float* olp = (const float*)d_in[4];  // original_log_trajectory_action_probs (T,)
    const float* tlp = (const float*)d_in[5];  // target_log_trajectory_task_action_probs (T,K)
    float* out = (float*)d_out;

    retrace_main<<<NBLOCKS, 256>>>(q, tq, tv, r, olp, tlp, out);
}

// round 7
// speedup vs baseline: 2.1782x; 1.1678x over previous
#include <cuda_runtime.h>
#include <cuda_bf16.h>

#define T_DIM 8192
#define K_DIM 2048
#define TM1   (T_DIM - 1)                      // 8191 rows in the loss
#define NTOT  ((long long)TM1 * K_DIM)         // 16,775,168 elements
#define GAMMA 0.99f
#define LOGG  (-0.0100503358535014f)           // logf(0.99)

#define NCHUNK       ((TM1 + 31) / 32)         // 256 row-chunks per column
#define SCAN_BLOCKS  256                       // FIRST block IDs -> spread over all SMs
#define QSUM_BLOCKS  888
#define NBLOCKS      (SCAN_BLOCKS + QSUM_BLOCKS)
#define FULLM        0xFFFFFFFFu

// Scratch (device globals are the allowed scratch mechanism).
// Transposed layout [k][t] so warp-over-rows access is coalesced.
__device__ float2       g_dp  [(long long)K_DIM * TM1];  // {decay, td*decay}
__device__ double       g_part[NBLOCKS];
__device__ unsigned int g_done;                          // zero-init; self-resetting

// smooth-L1: |d|<1 ? 0.5 d^2 : |d|-0.5  ==  m*(a - 0.5m) with a=|d|, m=min(a,1)
__device__ __forceinline__ float sl1(float pred, float target) {
    float a = fabsf(pred - target);
    float m = fminf(a, 1.0f);
    return m * (a - 0.5f * m);
}
__device__ __forceinline__ float sl1_acc(float acc, float d) {
    float a = fabsf(d);
    float m = fminf(a, 1.0f);
    return fmaf(m, fmaf(-0.5f, m, a), acc);
}

__global__ void __launch_bounds__(256, 8)
retrace_main(const float* __restrict__ q,
             const float* __restrict__ tq,
             const float* __restrict__ tv,
             const float* __restrict__ r,
             const float* __restrict__ olp,
             const float* __restrict__ tlp,
             float* __restrict__ out)
{
    const int tid  = threadIdx.x;
    const int lane = tid & 31;
    const int wrp  = tid >> 5;
    double acc = 0.0;

    // smem staging tiles: [buf][col 0..7][row 0..31], stride 36 so that
    // write addr = 36*c + r -> bank (4c + r) % 32 : conflict-free for c<8,r<4 pattern,
    // and read addr = 36*w + lane : conflict-free per warp.
    __shared__ float s_liw[2][8][36];   // reused as q-tile in the backward pass
    __shared__ float s_r  [2][8][36];
    __shared__ float s_tv [2][8][36];
    __shared__ float s_tq [2][8][36];
    __shared__ int   s_nch[8];

    if (blockIdx.x < SCAN_BLOCKS) {
        // ===== one WARP per column; tiles staged cooperatively (coalesced) =====
        const int k0 = blockIdx.x * 8;
        const int k  = k0 + wrp;
        const int lr = tid >> 3;        // staging row 0..31
        const int lc = tid & 7;         // staging col 0..7

        // ---- forward ----
        auto stage_f = [&](int buf, int cc) {
            const int  t = cc * 32 + lr;
            const bool v = t < TM1;
            const size_t o1 = (size_t)(t + 1) * K_DIM + k0 + lc;
            const size_t o0 = (size_t)t       * K_DIM + k0 + lc;
            s_liw[buf][lc][lr] = v ? tlp[o1] : 0.0f;
            s_r  [buf][lc][lr] = v ? r  [o0] : 0.0f;
            s_tv [buf][lc][lr] = v ? tv [o1] : 0.0f;
            s_tq [buf][lc][lr] = v ? tq [o1] : 0.0f;
        };

        float carry = 0.0f;
        int   tstop = TM1;
        bool  warp_dead = false;

        auto compch = [&](int buf, int cc) {
            const int  t = cc * 32 + lane;
            const bool v = t < TM1;
            float liw = s_liw[buf][wrp][lane] - (v ? olp[t + 1] : 0.0f);
            float m   = fminf(liw, 0.0f);
            float iw  = expf(m);
            float s   = v ? (LOGG + m) : 0.0f;
            #pragma unroll
            for (int off = 1; off < 32; off <<= 1) {      // inclusive prefix sum
                float u = __shfl_up_sync(FULLM, s, off);
                if (lane >= off) s += u;
            }
            float ls    = carry + s;
            float decay = expf(ls);                        // underflows to exact 0
            float pdv   = (s_r[buf][wrp][lane]
                           + GAMMA * (s_tv[buf][wrp][lane]
                                      - iw * s_tq[buf][wrp][lane])) * decay;
            if (v) g_dp[(size_t)k * TM1 + t] = make_float2(decay, pdv);
            carry = __shfl_sync(FULLM, ls, 31);
            unsigned bal = __ballot_sync(FULLM, v && decay == 0.0f);
            if (bal) { tstop = cc * 32 + (__ffs(bal) - 1); warp_dead = true; }
        };

        stage_f(0, 0);
        __syncthreads();
        {
            int cc = 0, buf = 0;
            while (true) {
                const bool last = (cc + 1 >= NCHUNK);
                if (!last) stage_f(buf ^ 1, cc + 1);       // prefetch next tile
                if (!warp_dead) compch(buf, cc);
                const bool allstop = __syncthreads_and(warp_dead) != 0;
                if (allstop || last) break;
                ++cc; buf ^= 1;
            }
        }

        // block-max chunk count for the cooperative backward staging
        const int nch = (tstop + 31) >> 5;
        if (lane == 0) s_nch[wrp] = nch;
        __syncthreads();
        int bmax = s_nch[0];
        #pragma unroll
        for (int i = 1; i < 8; ++i) bmax = max(bmax, s_nch[i]);
        __syncthreads();

        // ---- backward: q staged through smem; g_dp is [k][t]-coalesced ----
        auto stage_q = [&](int buf, int cc) {
            const int  t = cc * 32 + lr;
            const bool v = t < TM1;
            s_liw[buf][lc][lr] = v ? q[(size_t)t * K_DIM + k0 + lc] : 0.0f;
        };

        float Rcarry = 0.0f;
        if (bmax > 0) {
            stage_q(0, bmax - 1);
            __syncthreads();
            int buf = 0;
            for (int cc = bmax - 1; cc >= 0; --cc) {
                if (cc > 0) stage_q(buf ^ 1, cc - 1);
                if (cc < nch) {
                    const int  t = cc * 32 + lane;
                    const bool v = t < TM1;
                    float2 dp = v ? g_dp[(size_t)k * TM1 + t] : make_float2(0.0f, 0.0f);
                    float  qv = s_liw[buf][wrp][lane];
                    float  s  = dp.y;
                    #pragma unroll
                    for (int off = 1; off < 32; off <<= 1) {   // inclusive suffix sum
                        float u = __shfl_down_sync(FULLM, s, off);
                        if (lane + off < 32) s += u;
                    }
                    float R    = s + Rcarry;
                    float retr = R / fmaxf(dp.x, 1e-10f);
                    if (v) acc += (double)(sl1(qv, retr) - sl1(qv, 0.0f));
                    Rcarry = __shfl_sync(FULLM, R, 0);
                }
                __syncthreads();
                buf ^= 1;
            }
        }
    } else {
        // ------- elementwise sum of sl1(q, 0) over q[0 : TM1*K), MLP=4 -------
        const long long nvec   = NTOT / 4;               // divisible: K%4==0
        const float4*   q4     = (const float4*)q;
        long long       idx    = (long long)(blockIdx.x - SCAN_BLOCKS) * 256 + tid;
        const long long stride = (long long)QSUM_BLOCKS * 256;
        float f0 = 0.0f, f1 = 0.0f, f2 = 0.0f, f3 = 0.0f;
        for (; idx + 3 * stride < nvec; idx += 4 * stride) {
            float4 a = q4[idx];
            float4 b = q4[idx + stride];
            float4 c = q4[idx + 2 * stride];
            float4 d = q4[idx + 3 * stride];
            f0 = sl1_acc(sl1_acc(sl1_acc(sl1_acc(f0, a.x), a.y), a.z), a.w);
            f1 = sl1_acc(sl1_acc(sl1_acc(sl1_acc(f1, b.x), b.y), b.z), b.w);
            f2 = sl1_acc(sl1_acc(sl1_acc(sl1_acc(f2, c.x), c.y), c.z), c.w);
            f3 = sl1_acc(sl1_acc(sl1_acc(sl1_acc(f3, d.x), d.y), d.z), d.w);
        }
        for (; idx < nvec; idx += stride) {
            float4 a = q4[idx];
            f0 = sl1_acc(sl1_acc(sl1_acc(sl1_acc(f0, a.x), a.y), a.z), a.w);
        }
        acc = (double)((f0 + f1) + (f2 + f3));
    }

    // ---- deterministic block reduction: warp shuffle tree + fixed-order sum ----
    __shared__ double shw[8];
    #pragma unroll
    for (int off = 16; off > 0; off >>= 1)
        acc += __shfl_xor_sync(FULLM, acc, off);
    __syncthreads();                 // scan path used shw's bank region? distinct array; just order
    if (lane == 0) shw[wrp] = acc;
    __syncthreads();
    double blocksum = 0.0;
    if (tid == 0) {
        #pragma unroll
        for (int i = 0; i < 8; ++i) blocksum += shw[i];
    }

    // ---- fused last-block finalize (deterministic fixed-order final sum) ----
    __shared__ unsigned int sticket;
    if (tid == 0) {
        g_part[blockIdx.x] = blocksum;
        __threadfence();
        sticket = atomicAdd(&g_done, 1u);
    }
    __syncthreads();
    if (sticket == NBLOCKS - 1) {
        __threadfence();
        double a = 0.0;
        for (int i = tid; i < NBLOCKS; i += 256) a += g_part[i];
        __shared__ double sh[256];
        sh[tid] = a;
        __syncthreads();
        #pragma unroll
        for (int s = 128; s > 0; s >>= 1) {
            if (tid < s) sh[tid] += sh[tid + s];
            __syncthreads();
        }
        if (tid == 0) {
            out[0] = (float)(sh[0] / (double)NTOT);
            g_done = 0;                        // reset for next graph replay
        }
    }
}

extern "C" void kernel_launch(void* const* d_in, const int* in_sizes, int n_in,
                              void* d_out, int out_size)
{
    const float* q   = (const float*)d_in[0];  // state_trajectory_action_values (T,K)
    const float* tq  = (const float*)d_in[1];  // target_state_trajectory_action_values (T,K)
    const float* tv  = (const float*)d_in[2];  // target_expected_state_values (T,K)
    const float* r   = (const float*)d_in[3];  // rewards (T,K)
    const float* olp = (const float*)d_in[4];  // original_log_trajectory_action_probs (T,)
    const float* tlp = (const float*)d_in[5];  // target_log_trajectory_task_action_probs (T,K)
    float* out = (float*)d_out;

    retrace_main<<<NBLOCKS, 256>>>(q, tq, tv, r, olp, tlp, out);
}

// round 9
// speedup vs baseline: 2.5690x; 1.1794x over previous
#include <cuda_runtime.h>
#include <cuda_bf16.h>
#include <cstdint>

#define T_DIM 8192
#define K_DIM 2048
#define TM1   (T_DIM - 1)                      // 8191 rows in the loss
#define NTOT  ((long long)TM1 * K_DIM)         // 16,775,168 elements
#define GAMMA 0.99f
#define LOGG  (-0.0100503358535014f)           // logf(0.99)

#define SCAN_BLOCKS  256                       // FIRST block IDs -> spread over all SMs
#define QSUM_BLOCKS  888
#define NBLOCKS      (SCAN_BLOCKS + QSUM_BLOCKS)
#define FULLM        0xFFFFFFFFu

#define RPAD   68                              // rows-per-col stride (64 + 4): conflict-free
#define NRND   128                             // 128 rounds x 64 rows = 8192 >= TM1

// Scratch (device globals are the allowed scratch mechanism).
// Transposed layout [k][t] so warp-over-rows access is coalesced.
__device__ float2       g_dp  [(long long)K_DIM * TM1];  // {decay, td*decay}
__device__ double       g_part[NBLOCKS];
__device__ unsigned int g_done;                          // zero-init; self-resetting

__device__ __forceinline__ float sl1(float pred, float target) {
    float a = fabsf(pred - target);
    float m = fminf(a, 1.0f);
    return m * (a - 0.5f * m);
}
__device__ __forceinline__ float sl1_acc(float acc, float d) {
    float a = fabsf(d);
    float m = fminf(a, 1.0f);
    return fmaf(m, fmaf(-0.5f, m, a), acc);
}

__device__ __forceinline__ unsigned int smem_u32(const void* p) {
    return (unsigned int)__cvta_generic_to_shared(p);
}
__device__ __forceinline__ void cpa4(unsigned int dst, const float* src) {
    asm volatile("cp.async.ca.shared.global [%0], [%1], 4;" :: "r"(dst), "l"(src));
}
#define CPC()  asm volatile("cp.async.commit_group;")
#define CPW(n) asm volatile("cp.async.wait_group %0;" :: "n"(n))

__global__ void __launch_bounds__(256, 8)
retrace_main(const float* __restrict__ q,
             const float* __restrict__ tq,
             const float* __restrict__ tv,
             const float* __restrict__ r,
             const float* __restrict__ olp,
             const float* __restrict__ tlp,
             float* __restrict__ out)
{
    const int tid  = threadIdx.x;
    const int lane = tid & 31;
    const int wrp  = tid >> 5;
    double acc = 0.0;

    // staging tiles: [buf][col*RPAD + row], 64 rows/round, 8 cols.
    // cp.async write bank = (RPAD*c + r) % 32 = (4c + r) % 32 : 32 distinct per warp.
    // warp read bank = (RPAD*wrp + base + lane) % 32 : consecutive, conflict-free.
    __shared__ float s_liw[2][8 * RPAD];    // reused as q tile in the backward pass
    __shared__ float s_r  [2][8 * RPAD];
    __shared__ float s_tv [2][8 * RPAD];
    __shared__ float s_tq [2][8 * RPAD];
    __shared__ int   s_nch[8];

    if (blockIdx.x < SCAN_BLOCKS) {
        // ===== one WARP per column; 64-row rounds staged via cp.async, 2-deep =====
        const int k0 = blockIdx.x * 8;
        const int k  = k0 + wrp;

        float carry = 0.0f;
        int   tstop = TM1;
        bool  warp_dead = false;

        // ---- forward staging: 2 cp.async x 4 arrays per thread per round ----
        auto stage_f = [&](int buf, int rnd) {
            #pragma unroll
            for (int i = 0; i < 2; ++i) {
                const int idx = tid + 256 * i;
                const int row = idx >> 3, col = idx & 7;
                const int t  = rnd * 64 + row;
                const int tc = min(t, TM1 - 1);          // clamp; invalid lanes masked later
                const unsigned int d = (unsigned int)(col * RPAD + row) * 4u;
                cpa4(smem_u32(&s_liw[buf][0]) + d, tlp + (size_t)(tc + 1) * K_DIM + k0 + col);
                cpa4(smem_u32(&s_r  [buf][0]) + d, r   + (size_t)tc       * K_DIM + k0 + col);
                cpa4(smem_u32(&s_tv [buf][0]) + d, tv  + (size_t)(tc + 1) * K_DIM + k0 + col);
                cpa4(smem_u32(&s_tq [buf][0]) + d, tq  + (size_t)(tc + 1) * K_DIM + k0 + col);
            }
        };
        // ---- one 32-row scan step (sub-chunk s of round rnd) ----
        auto comp_sub = [&](int buf, int rnd, int s) {
            const int  sc = rnd * 2 + s;
            const int  t  = sc * 32 + lane;
            const bool v  = t < TM1;
            const int  ro = s * 32 + lane;
            float liw = s_liw[buf][wrp * RPAD + ro] - (v ? olp[t + 1] : 0.0f);
            float m   = fminf(liw, 0.0f);
            float iw  = expf(m);
            float sv  = v ? (LOGG + m) : 0.0f;
            #pragma unroll
            for (int off = 1; off < 32; off <<= 1) {     // inclusive prefix sum
                float u = __shfl_up_sync(FULLM, sv, off);
                if (lane >= off) sv += u;
            }
            float ls    = carry + sv;
            float decay = expf(ls);                       // underflows to exact 0
            float pdv   = (s_r[buf][wrp * RPAD + ro]
                           + GAMMA * (s_tv[buf][wrp * RPAD + ro]
                                      - iw * s_tq[buf][wrp * RPAD + ro])) * decay;
            if (v) g_dp[(size_t)k * TM1 + t] = make_float2(decay, pdv);
            carry = __shfl_sync(FULLM, ls, 31);
            unsigned bal = __ballot_sync(FULLM, v && decay == 0.0f);
            if (bal && !warp_dead) { tstop = sc * 32 + (__ffs(bal) - 1); warp_dead = true; }
        };

        stage_f(0, 0); CPC();
        stage_f(1, 1); CPC();
        int rnd = 0;
        while (true) {
            CPW(1);                                       // round rnd's tiles landed
            __syncthreads();
            const int buf = rnd & 1;
            if (!warp_dead) comp_sub(buf, rnd, 0);
            if (!warp_dead) comp_sub(buf, rnd, 1);
            const bool allstop = __syncthreads_and(warp_dead) != 0;  // also frees buf
            if (allstop || rnd + 1 >= NRND) break;
            if (rnd + 2 < NRND) stage_f(buf, rnd + 2);
            CPC();                                        // commit (possibly empty) group
            ++rnd;
        }

        // block-max sub-chunk count for cooperative backward staging
        const int nch = (tstop + 31) >> 5;
        if (lane == 0) s_nch[wrp] = nch;
        __syncthreads();
        int bmax = s_nch[0];
        #pragma unroll
        for (int i = 1; i < 8; ++i) bmax = max(bmax, s_nch[i]);
        const int rmax = (bmax + 1) >> 1;                 // 64-row rounds, >= 1

        // ---- backward: q tiles via cp.async one round ahead; g_dp direct ----
        auto stage_q = [&](int buf, int rr) {
            #pragma unroll
            for (int i = 0; i < 2; ++i) {
                const int idx = tid + 256 * i;
                const int row = idx >> 3, col = idx & 7;
                const int tc  = min(rr * 64 + row, TM1 - 1);
                cpa4(smem_u32(&s_liw[buf][0]) + (unsigned int)(col * RPAD + row) * 4u,
                     q + (size_t)tc * K_DIM + k0 + col);
            }
        };

        CPW(0);                                           // drain forward leftovers
        __syncthreads();                                  // buffers free for q tiles
        float Rcarry = 0.0f;
        stage_q((rmax - 1) & 1, rmax - 1); CPC();
        for (int rr = rmax - 1; ; --rr) {
            if (rr > 0) { stage_q((rr - 1) & 1, rr - 1); CPC(); CPW(1); }
            else        { CPW(0); }
            __syncthreads();                              // q tile for round rr visible
            const int buf = rr & 1;
            // issue both sub-chunk dp loads up front (independent)
            const int sc1 = 2 * rr + 1, sc0 = 2 * rr;
            const int t1 = sc1 * 32 + lane, t0 = sc0 * 32 + lane;
            const bool v1 = (sc1 < nch) && (t1 < TM1);
            const bool v0 = (sc0 < nch) && (t0 < TM1);
            float2 dp1 = make_float2(0.0f, 0.0f), dp0 = make_float2(0.0f, 0.0f);
            if (v1) dp1 = g_dp[(size_t)k * TM1 + t1];
            if (v0) dp0 = g_dp[(size_t)k * TM1 + t0];
            // hi sub-chunk: inclusive suffix sum
            {
                float s = dp1.y;
                #pragma unroll
                for (int off = 1; off < 32; off <<= 1) {
                    float u = __shfl_down_sync(FULLM, s, off);
                    if (lane + off < 32) s += u;
                }
                float R    = s + Rcarry;
                float retr = R / fmaxf(dp1.x, 1e-10f);
                float qv   = s_liw[buf][wrp * RPAD + 32 + lane];
                if (v1) acc += (double)(sl1(qv, retr) - sl1(qv, 0.0f));
                Rcarry = __shfl_sync(FULLM, R, 0);
            }
            // lo sub-chunk
            {
                float s = dp0.y;
                #pragma unroll
                for (int off = 1; off < 32; off <<= 1) {
                    float u = __shfl_down_sync(FULLM, s, off);
                    if (lane + off < 32) s += u;
                }
                float R    = s + Rcarry;
                float retr = R / fmaxf(dp0.x, 1e-10f);
                float qv   = s_liw[buf][wrp * RPAD + lane];
                if (v0) acc += (double)(sl1(qv, retr) - sl1(qv, 0.0f));
                Rcarry = __shfl_sync(FULLM, R, 0);
            }
            if (rr == 0) break;
            __syncthreads();                              // round rr consumed; buf reusable
        }
    } else {
        // ------- elementwise sum of sl1(q, 0) over q[0 : TM1*K), MLP=4 -------
        const long long nvec   = NTOT / 4;               // divisible: K%4==0
        const float4*   q4     = (const float4*)q;
        long long       idx    = (long long)(blockIdx.x - SCAN_BLOCKS) * 256 + tid;
        const long long stride = (long long)QSUM_BLOCKS * 256;
        float f0 = 0.0f, f1 = 0.0f, f2 = 0.0f, f3 = 0.0f;
        for (; idx + 3 * stride < nvec; idx += 4 * stride) {
            float4 a = q4[idx];
            float4 b = q4[idx + stride];
            float4 c = q4[idx + 2 * stride];
            float4 d = q4[idx + 3 * stride];
            f0 = sl1_acc(sl1_acc(sl1_acc(sl1_acc(f0, a.x), a.y), a.z), a.w);
            f1 = sl1_acc(sl1_acc(sl1_acc(sl1_acc(f1, b.x), b.y), b.z), b.w);
            f2 = sl1_acc(sl1_acc(sl1_acc(sl1_acc(f2, c.x), c.y), c.z), c.w);
            f3 = sl1_acc(sl1_acc(sl1_acc(sl1_acc(f3, d.x), d.y), d.z), d.w);
        }
        for (; idx < nvec; idx += stride) {
            float4 a = q4[idx];
            f0 = sl1_acc(sl1_acc(sl1_acc(sl1_acc(f0, a.x), a.y), a.z), a.w);
        }
        acc = (double)((f0 + f1) + (f2 + f3));
    }

    // ---- deterministic block reduction: warp shuffle tree + fixed-order sum ----
    __shared__ double shw[8];
    #pragma unroll
    for (int off = 16; off > 0; off >>= 1)
        acc += __shfl_xor_sync(FULLM, acc, off);
    __syncthreads();
    if (lane == 0) shw[wrp] = acc;
    __syncthreads();
    double blocksum = 0.0;
    if (tid == 0) {
        #pragma unroll
        for (int i = 0; i < 8; ++i) blocksum += shw[i];
    }

    // ---- fused last-block finalize (deterministic fixed-order final sum) ----
    __shared__ unsigned int sticket;
    if (tid == 0) {
        g_part[blockIdx.x] = blocksum;
        __threadfence();
        sticket = atomicAdd(&g_done, 1u);
    }
    __syncthreads();
    if (sticket == NBLOCKS - 1) {
        __threadfence();
        double a = 0.0;
        for (int i = tid; i < NBLOCKS; i += 256) a += g_part[i];
        __shared__ double sh[256];
        sh[tid] = a;
        __syncthreads();
        #pragma unroll
        for (int s = 128; s > 0; s >>= 1) {
            if (tid < s) sh[tid] += sh[tid + s];
            __syncthreads();
        }
        if (tid == 0) {
            out[0] = (float)(sh[0] / (double)NTOT);
            g_done = 0;                        // reset for next graph replay
        }
    }
}

extern "C" void kernel_launch(void* const* d_in, const int* in_sizes, int n_in,
                              void* d_out, int out_size)
{
    const float* q   = (const float*)d_in[0];  // state_trajectory_action_values (T,K)
    const float* tq  = (const float*)d_in[1];  // target_state_trajectory_action_values (T,K)
    const float* tv  = (const float*)d_in[2];  // target_expected_state_values (T,K)
    const float* r   = (const float*)d_in[3];  // rewards (T,K)
    const float* olp = (const float*)d_in[4];  // original_log_trajectory_action_probs (T,)
    const float* tlp = (const float*)d_in[5];  // target_log_trajectory_task_action_probs (T,K)
    float* out = (float*)d_out;

    retrace_main<<<NBLOCKS, 256>>>(q, tq, tv, r, olp, tlp, out);
}